// round 4
// baseline (speedup 1.0000x reference)
#include <cuda_runtime.h>
#include <cuda_bf16.h>
#include <cstdint>

#define NPTS 512000
#define KDIM 64000
#define EPS 1e-5f

// ---------------- device scratch (no allocation allowed) ----------------
__device__ float g_h1[NPTS * 16];
__device__ float g_h2[NPTS * 8];
__device__ float g_scr[NPTS];
__device__ float g_pa1[1000 * 32];
__device__ float g_pa2[1000 * 16];
__device__ float g_pa3[1000 * 2];
__device__ float g_bn1[32], g_bn2[16], g_bn3[2];
__device__ __nv_bfloat16 g_Ahi[256 * KDIM];
__device__ __nv_bfloat16 g_Alo[256 * KDIM];
__device__ float g_part[9 * 256 * 1024];
__device__ float g_a1[256 * 1024];
__device__ float g_c2[256 * 256];

// ---------------- helpers ----------------
__device__ __forceinline__ float warp_sum(float v) {
#pragma unroll
    for (int o = 16; o; o >>= 1) v += __shfl_down_sync(0xffffffffu, v, o);
    return v;
}
__device__ __forceinline__ float warp_max(float v) {
#pragma unroll
    for (int o = 16; o; o >>= 1) v = fmaxf(v, __shfl_down_sync(0xffffffffu, v, o));
    return v;
}
__device__ __forceinline__ uint32_t s2u(const void* p) {
    uint32_t a;
    asm("{ .reg .u64 t; cvta.to.shared.u64 t, %1; cvt.u32.u64 %0, t; }" : "=r"(a) : "l"(p));
    return a;
}
__device__ __forceinline__ uint32_t pack2(__nv_bfloat16 a, __nv_bfloat16 b) {
    return ((uint32_t)__bfloat16_as_ushort(b) << 16) | (uint32_t)__bfloat16_as_ushort(a);
}

#define MMA(d, a, b0, b1)                                                        \
    asm volatile(                                                                \
        "mma.sync.aligned.m16n8k16.row.col.f32.bf16.bf16.f32 "                   \
        "{%0,%1,%2,%3},{%4,%5,%6,%7},{%8,%9},{%0,%1,%2,%3};"                     \
        : "+f"(d[0]), "+f"(d[1]), "+f"(d[2]), "+f"(d[3])                         \
        : "r"(a[0]), "r"(a[1]), "r"(a[2]), "r"(a[3]), "r"(b0), "r"(b1))

// ---------------- front-end: pointwise MLP with global BN stats ----------------
__global__ __launch_bounds__(256) void k_att1(const float* __restrict__ x,
                                              const float* __restrict__ w1,
                                              const float* __restrict__ b1) {
    __shared__ float sw[512], sb[16];
    __shared__ float rs[16][8], rq[16][8];
    int tid = threadIdx.x, wid = tid >> 5, lane = tid & 31;
    for (int i = tid; i < 512; i += 256) sw[i] = w1[i];
    if (tid < 16) sb[tid] = b1[tid];
    __syncthreads();
    float ls[16], lq[16];
#pragma unroll
    for (int j = 0; j < 16; ++j) { ls[j] = 0.f; lq[j] = 0.f; }
    size_t base = (size_t)blockIdx.x * 512;
    for (int r = 0; r < 2; ++r) {
        size_t pt = base + tid + r * 256;
        const float4* xp = (const float4*)(x + pt * 32);
        float xv[32];
#pragma unroll
        for (int q = 0; q < 8; ++q) {
            float4 t = __ldg(xp + q);
            xv[q * 4] = t.x; xv[q * 4 + 1] = t.y; xv[q * 4 + 2] = t.z; xv[q * 4 + 3] = t.w;
        }
#pragma unroll
        for (int j = 0; j < 16; ++j) {
            float a = sb[j];
#pragma unroll
            for (int c = 0; c < 32; ++c) a = fmaf(xv[c], sw[j * 32 + c], a);
            g_h1[pt * 16 + j] = a;
            ls[j] += a; lq[j] += a * a;
        }
    }
#pragma unroll
    for (int j = 0; j < 16; ++j) {
        float s = warp_sum(ls[j]), q = warp_sum(lq[j]);
        if (lane == 0) { rs[j][wid] = s; rq[j][wid] = q; }
    }
    __syncthreads();
    if (tid < 16) {
        float s = 0.f, q = 0.f;
#pragma unroll
        for (int w = 0; w < 8; ++w) { s += rs[tid][w]; q += rq[tid][w]; }
        g_pa1[blockIdx.x * 32 + tid] = s;
        g_pa1[blockIdx.x * 32 + 16 + tid] = q;
    }
}

__global__ __launch_bounds__(1024) void k_bnred(int which, int nch,
                                                const float* __restrict__ g,
                                                const float* __restrict__ be) {
    const float* part = which == 0 ? g_pa1 : which == 1 ? g_pa2 : g_pa3;
    float* out = which == 0 ? g_bn1 : which == 1 ? g_bn2 : g_bn3;
    int w = threadIdx.x >> 5, lane = threadIdx.x & 31;
    __shared__ float tot[64];
    int stride = 2 * nch;
    if (w < stride) {
        float s = 0.f;
        for (int i = lane; i < 1000; i += 32) s += part[i * stride + w];
        s = warp_sum(s);
        if (!lane) tot[w] = s;
    }
    __syncthreads();
    if ((int)threadIdx.x < nch) {
        int j = threadIdx.x;
        float mean = tot[j] * (1.f / 512000.f);
        float var = tot[nch + j] * (1.f / 512000.f) - mean * mean;
        float sc = rsqrtf(var + EPS) * g[j];
        out[j] = sc;
        out[nch + j] = be[j] - mean * sc;
    }
}

__global__ __launch_bounds__(256) void k_att2(const float* __restrict__ w2,
                                              const float* __restrict__ b2) {
    __shared__ float sw[128], sb[8], ssc[16], ssh[16];
    __shared__ float rs[8][8], rq[8][8];
    int tid = threadIdx.x, wid = tid >> 5, lane = tid & 31;
    for (int i = tid; i < 128; i += 256) sw[i] = w2[i];
    if (tid < 8) sb[tid] = b2[tid];
    if (tid < 16) { ssc[tid] = g_bn1[tid]; ssh[tid] = g_bn1[16 + tid]; }
    __syncthreads();
    float ls[8], lq[8];
#pragma unroll
    for (int j = 0; j < 8; ++j) { ls[j] = 0.f; lq[j] = 0.f; }
    size_t base = (size_t)blockIdx.x * 512;
    for (int r = 0; r < 2; ++r) {
        size_t pt = base + tid + r * 256;
        float ha[16];
#pragma unroll
        for (int c = 0; c < 16; ++c)
            ha[c] = fmaxf(0.f, fmaf(g_h1[pt * 16 + c], ssc[c], ssh[c]));
#pragma unroll
        for (int j = 0; j < 8; ++j) {
            float a = sb[j];
#pragma unroll
            for (int c = 0; c < 16; ++c) a = fmaf(ha[c], sw[j * 16 + c], a);
            g_h2[pt * 8 + j] = a;
            ls[j] += a; lq[j] += a * a;
        }
    }
#pragma unroll
    for (int j = 0; j < 8; ++j) {
        float s = warp_sum(ls[j]), q = warp_sum(lq[j]);
        if (lane == 0) { rs[j][wid] = s; rq[j][wid] = q; }
    }
    __syncthreads();
    if (tid < 8) {
        float s = 0.f, q = 0.f;
#pragma unroll
        for (int w = 0; w < 8; ++w) { s += rs[tid][w]; q += rq[tid][w]; }
        g_pa2[blockIdx.x * 16 + tid] = s;
        g_pa2[blockIdx.x * 16 + 8 + tid] = q;
    }
}

__global__ __launch_bounds__(256) void k_att3(const float* __restrict__ w3,
                                              const float* __restrict__ b3) {
    __shared__ float sw[8], ssc[8], ssh[8], sb3;
    __shared__ float rs[8], rq[8];
    int tid = threadIdx.x, wid = tid >> 5, lane = tid & 31;
    if (tid < 8) { sw[tid] = w3[tid]; ssc[tid] = g_bn2[tid]; ssh[tid] = g_bn2[8 + tid]; }
    if (tid == 0) sb3 = b3[0];
    __syncthreads();
    float ls = 0.f, lq = 0.f;
    size_t base = (size_t)blockIdx.x * 512;
    for (int r = 0; r < 2; ++r) {
        size_t pt = base + tid + r * 256;
        float a = sb3;
#pragma unroll
        for (int c = 0; c < 8; ++c)
            a = fmaf(fmaxf(0.f, fmaf(g_h2[pt * 8 + c], ssc[c], ssh[c])), sw[c], a);
        g_scr[pt] = a;
        ls += a; lq += a * a;
    }
    ls = warp_sum(ls); lq = warp_sum(lq);
    if (lane == 0) { rs[wid] = ls; rq[wid] = lq; }
    __syncthreads();
    if (tid == 0) {
        float s = 0.f, q = 0.f;
#pragma unroll
        for (int w = 0; w < 8; ++w) { s += rs[w]; q += rq[w]; }
        g_pa3[blockIdx.x * 2] = s;
        g_pa3[blockIdx.x * 2 + 1] = q;
    }
}

// ---------------- per-segment softmax + pooled A in bf16 hi/lo ----------------
__global__ __launch_bounds__(256) void k_pool(const float* __restrict__ x) {
    __shared__ float s[2000];
    __shared__ float red[8];
    __shared__ float m_sh, sum_sh;
    int b = blockIdx.x, tid = threadIdx.x, wid = tid >> 5, lane = tid & 31;
    float sc = g_bn3[0], sh = g_bn3[1];
    float lm = -1e30f;
    for (int p = tid; p < 2000; p += 256) {
        float v = fmaxf(0.f, fmaf(g_scr[(size_t)b * 2000 + p], sc, sh));
        s[p] = v;
        lm = fmaxf(lm, v);
    }
    lm = warp_max(lm);
    if (!lane) red[wid] = lm;
    __syncthreads();
    if (tid == 0) {
        float m = red[0];
#pragma unroll
        for (int i = 1; i < 8; ++i) m = fmaxf(m, red[i]);
        m_sh = m;
    }
    __syncthreads();
    float m = m_sh, le = 0.f;
    for (int p = tid; p < 2000; p += 256) {
        float e = expf(s[p] - m);
        s[p] = e;
        le += e;
    }
    le = warp_sum(le);
    if (!lane) red[wid] = le;
    __syncthreads();
    if (tid == 0) {
        float t = 0.f;
#pragma unroll
        for (int i = 0; i < 8; ++i) t += red[i];
        sum_sh = t;
    }
    __syncthreads();
    float inv = 1.f / sum_sh;
    for (int p = tid; p < 2000; p += 256) {
        float a = s[p] * inv;
        const float4* xp = (const float4*)(x + ((size_t)b * 2000 + p) * 32);
        size_t ob = (size_t)b * KDIM + (size_t)p * 32;
#pragma unroll
        for (int q = 0; q < 8; ++q) {
            float4 t = xp[q];
            float v0 = t.x * a, v1 = t.y * a, v2 = t.z * a, v3 = t.w * a;
            __nv_bfloat16 h0 = __float2bfloat16(v0), h1 = __float2bfloat16(v1);
            __nv_bfloat16 h2 = __float2bfloat16(v2), h3 = __float2bfloat16(v3);
            __nv_bfloat16 l0 = __float2bfloat16(v0 - __bfloat162float(h0));
            __nv_bfloat16 l1 = __float2bfloat16(v1 - __bfloat162float(h1));
            __nv_bfloat16 l2 = __float2bfloat16(v2 - __bfloat162float(h2));
            __nv_bfloat16 l3 = __float2bfloat16(v3 - __bfloat162float(h3));
            ((uint2*)(g_Ahi + ob))[q] = make_uint2(pack2(h0, h1), pack2(h2, h3));
            ((uint2*)(g_Alo + ob))[q] = make_uint2(pack2(l0, l1), pack2(l2, l3));
        }
    }
}

// ---------------- fc1 GEMM: 256x1024x64000, bf16 3-term split, split-K=9 ----------------
// smem per buffer: Ahi 256x48B, Alo 256x48B, Whi 64x48B, Wlo 64x48B = 30720B; x2 buffers
#define BUFB 30720
__global__ __launch_bounds__(256, 1) void k_gemm(const float* __restrict__ fw1) {
    extern __shared__ char sm[];
    int tid = threadIdx.x, lane = tid & 31, wid = tid >> 5;
    int n0 = blockIdx.x * 64, split = blockIdx.y;
    int kbeg = split * 7120;
    int kend = min(KDIM, kbeg + 7120);
    int steps = (kend - kbeg) >> 4;
    int wm = wid * 32;
    int r0 = lane >> 2, c0 = (lane & 3) * 2;

    float acc[2][8][4];
#pragma unroll
    for (int a = 0; a < 2; ++a)
#pragma unroll
        for (int b = 0; b < 8; ++b)
#pragma unroll
            for (int c = 0; c < 4; ++c) acc[a][b][c] = 0.f;

    // --- staging lambdas ---
    auto cpA = [&](char* dst, int k0) {
#pragma unroll
        for (int i = 0; i < 4; ++i) {
            int cid = tid + i * 256;
            int plane = cid >> 9, row = (cid >> 1) & 255, half = cid & 1;
            const __nv_bfloat16* src =
                (plane ? g_Alo : g_Ahi) + (size_t)row * KDIM + k0 + half * 8;
            uint32_t d = s2u(dst + plane * 12288 + row * 48 + half * 16);
            asm volatile("cp.async.cg.shared.global [%0],[%1],16;" ::"r"(d), "l"(src));
        }
    };
    int wr = tid >> 2, wq = tid & 3;
    auto ldW = [&](int k0) {
        return *(const float4*)(fw1 + (size_t)(n0 + wr) * KDIM + k0 + wq * 4);
    };
    auto stW = [&](char* dst, float4 v) {
        __nv_bfloat16 h0 = __float2bfloat16(v.x), h1 = __float2bfloat16(v.y);
        __nv_bfloat16 h2 = __float2bfloat16(v.z), h3 = __float2bfloat16(v.w);
        __nv_bfloat16 l0 = __float2bfloat16(v.x - __bfloat162float(h0));
        __nv_bfloat16 l1 = __float2bfloat16(v.y - __bfloat162float(h1));
        __nv_bfloat16 l2 = __float2bfloat16(v.z - __bfloat162float(h2));
        __nv_bfloat16 l3 = __float2bfloat16(v.w - __bfloat162float(h3));
        *(uint2*)(dst + 24576 + wr * 48 + wq * 8) = make_uint2(pack2(h0, h1), pack2(h2, h3));
        *(uint2*)(dst + 27648 + wr * 48 + wq * 8) = make_uint2(pack2(l0, l1), pack2(l2, l3));
    };

    // prologue
    cpA(sm, kbeg);
    asm volatile("cp.async.commit_group;" ::: "memory");
    stW(sm, ldW(kbeg));

    for (int s = 0; s < steps; ++s) {
        char* cur = sm + (s & 1) * BUFB;
        char* nxt = sm + ((s + 1) & 1) * BUFB;
        float4 wv;
        bool more = (s + 1 < steps);
        if (more) {
            cpA(nxt, kbeg + (s + 1) * 16);
            asm volatile("cp.async.commit_group;" ::: "memory");
            wv = ldW(kbeg + (s + 1) * 16);
        }
        if (more) asm volatile("cp.async.wait_group 1;" ::: "memory");
        else      asm volatile("cp.async.wait_group 0;" ::: "memory");
        __syncthreads();

        // A fragments (hi/lo) for this warp's 2 m16 tiles
        uint32_t aH[2][4], aL[2][4];
#pragma unroll
        for (int mi = 0; mi < 2; ++mi) {
            int rb = wm + mi * 16;
#pragma unroll
            for (int rg = 0; rg < 4; ++rg) {
                int row = rb + r0 + (rg & 1) * 8;
                int col = c0 + (rg >> 1) * 8;
                aH[mi][rg] = *(const uint32_t*)(cur + row * 48 + col * 2);
                aL[mi][rg] = *(const uint32_t*)(cur + 12288 + row * 48 + col * 2);
            }
        }
#pragma unroll
        for (int ni = 0; ni < 8; ++ni) {
            int n = ni * 8 + r0;
            uint32_t bH0 = *(const uint32_t*)(cur + 24576 + n * 48 + c0 * 2);
            uint32_t bH1 = *(const uint32_t*)(cur + 24576 + n * 48 + (c0 + 8) * 2);
            uint32_t bL0 = *(const uint32_t*)(cur + 27648 + n * 48 + c0 * 2);
            uint32_t bL1 = *(const uint32_t*)(cur + 27648 + n * 48 + (c0 + 8) * 2);
#pragma unroll
            for (int mi = 0; mi < 2; ++mi) {
                MMA(acc[mi][ni], aH[mi], bH0, bH1);
                MMA(acc[mi][ni], aH[mi], bL0, bL1);
                MMA(acc[mi][ni], aL[mi], bH0, bH1);
            }
        }
        if (more) stW(nxt, wv);
        __syncthreads();
    }

    // epilogue: split-K partials
    float* dst = g_part + (size_t)split * 256 * 1024;
#pragma unroll
    for (int mi = 0; mi < 2; ++mi) {
#pragma unroll
        for (int ni = 0; ni < 8; ++ni) {
            int row = wm + mi * 16 + r0;
            int col = n0 + ni * 8 + (lane & 3) * 2;
            *(float2*)(dst + (size_t)row * 1024 + col) =
                make_float2(acc[mi][ni][0], acc[mi][ni][1]);
            *(float2*)(dst + (size_t)(row + 8) * 1024 + col) =
                make_float2(acc[mi][ni][2], acc[mi][ni][3]);
        }
    }
}

// ---------------- reduce split-K + BN + relu ----------------
__global__ __launch_bounds__(256) void k_fc1red(const float* __restrict__ fb1,
                                                const float* __restrict__ fg1,
                                                const float* __restrict__ fbe1) {
    int col = blockIdx.x, r = threadIdx.x;
    int w = r >> 5, lane = r & 31;
    float v = fb1[col];
#pragma unroll
    for (int s = 0; s < 9; ++s) v += g_part[(size_t)(s * 256 + r) * 1024 + col];
    __shared__ float red[16];
    __shared__ float mv[2];
    float s1 = warp_sum(v), s2 = warp_sum(v * v);
    if (!lane) { red[w] = s1; red[8 + w] = s2; }
    __syncthreads();
    if (r == 0) {
        float a = 0.f, b = 0.f;
#pragma unroll
        for (int i = 0; i < 8; ++i) { a += red[i]; b += red[8 + i]; }
        float m = a * (1.f / 256.f);
        mv[0] = m;
        mv[1] = b * (1.f / 256.f) - m * m;
    }
    __syncthreads();
    float sc = rsqrtf(mv[1] + EPS) * fg1[col];
    float sh = fbe1[col] - mv[0] * sc;
    g_a1[(size_t)r * 1024 + col] = fmaxf(0.f, fmaf(v, sc, sh));
}

// ---------------- fc2: [256,1024]@[1024,256] tiled SIMT ----------------
__global__ __launch_bounds__(256) void k_fc2(const float* __restrict__ fw2,
                                             const float* __restrict__ fb2) {
    __shared__ float sa[32][129], sw[32][129];
    int tid = threadIdx.x;
    int rt = blockIdx.x >> 3, ct = blockIdx.x & 7;
    int tx = tid & 31, ty = tid >> 5;
    float accv[4] = {0.f, 0.f, 0.f, 0.f};
    for (int kc = 0; kc < 1024; kc += 128) {
#pragma unroll
        for (int i = 0; i < 4; ++i) {
            int id = tid + i * 256;
            int row = id >> 5, q = id & 31;
            float4 va = *(const float4*)(g_a1 + (size_t)(rt * 32 + row) * 1024 + kc + q * 4);
            sa[row][q * 4 + 0] = va.x; sa[row][q * 4 + 1] = va.y;
            sa[row][q * 4 + 2] = va.z; sa[row][q * 4 + 3] = va.w;
            float4 vw = *(const float4*)(fw2 + (size_t)(ct * 32 + row) * 1024 + kc + q * 4);
            sw[row][q * 4 + 0] = vw.x; sw[row][q * 4 + 1] = vw.y;
            sw[row][q * 4 + 2] = vw.z; sw[row][q * 4 + 3] = vw.w;
        }
        __syncthreads();
#pragma unroll 8
        for (int k = 0; k < 128; ++k) {
            float wv = sw[tx][k];
#pragma unroll
            for (int i = 0; i < 4; ++i) accv[i] = fmaf(sa[ty + 8 * i][k], wv, accv[i]);
        }
        __syncthreads();
    }
    float bias = fb2[ct * 32 + tx];
#pragma unroll
    for (int i = 0; i < 4; ++i)
        g_c2[(size_t)(rt * 32 + ty + 8 * i) * 256 + ct * 32 + tx] = accv[i] + bias;
}

__global__ __launch_bounds__(256) void k_bnf2(const float* __restrict__ fg2,
                                              const float* __restrict__ fbe2) {
    int n = blockIdx.x, r = threadIdx.x, w = r >> 5, lane = r & 31;
    float v = g_c2[(size_t)r * 256 + n];
    __shared__ float red[16];
    __shared__ float mv[2];
    float s1 = warp_sum(v), s2 = warp_sum(v * v);
    if (!lane) { red[w] = s1; red[8 + w] = s2; }
    __syncthreads();
    if (r == 0) {
        float a = 0.f, b = 0.f;
#pragma unroll
        for (int i = 0; i < 8; ++i) { a += red[i]; b += red[8 + i]; }
        float m = a * (1.f / 256.f);
        mv[0] = m;
        mv[1] = b * (1.f / 256.f) - m * m;
    }
    __syncthreads();
    float sc = rsqrtf(mv[1] + EPS) * fg2[n];
    float sh = fbe2[n] - mv[0] * sc;
    g_c2[(size_t)r * 256 + n] = fmaxf(0.f, fmaf(v, sc, sh));
}

__global__ __launch_bounds__(256) void k_norm(float* __restrict__ out) {
    int row = blockIdx.x, c = threadIdx.x, w = c >> 5, lane = c & 31;
    float v = g_c2[(size_t)row * 256 + c];
    __shared__ float red[8];
    __shared__ float nrm;
    float s = warp_sum(v * v);
    if (!lane) red[w] = s;
    __syncthreads();
    if (c == 0) {
        float t = 0.f;
#pragma unroll
        for (int i = 0; i < 8; ++i) t += red[i];
        nrm = fmaxf(sqrtf(t), 1e-12f);
    }
    __syncthreads();
    out[(size_t)row * 256 + c] = v / nrm;
}

// ---------------- launch ----------------
extern "C" void kernel_launch(void* const* d_in, const int* in_sizes, int n_in,
                              void* d_out, int out_size) {
    const float* x   = (const float*)d_in[0];
    const float* w1  = (const float*)d_in[2];
    const float* b1  = (const float*)d_in[3];
    const float* g1  = (const float*)d_in[4];
    const float* be1 = (const float*)d_in[5];
    const float* w2  = (const float*)d_in[6];
    const float* b2  = (const float*)d_in[7];
    const float* g2  = (const float*)d_in[8];
    const float* be2 = (const float*)d_in[9];
    const float* w3  = (const float*)d_in[10];
    const float* b3  = (const float*)d_in[11];
    const float* g3  = (const float*)d_in[12];
    const float* be3 = (const float*)d_in[13];
    const float* fw1 = (const float*)d_in[14];
    const float* fb1 = (const float*)d_in[15];
    const float* fg1 = (const float*)d_in[16];
    const float* fbe1= (const float*)d_in[17];
    const float* fw2 = (const float*)d_in[18];
    const float* fb2 = (const float*)d_in[19];
    const float* fg2 = (const float*)d_in[20];
    const float* fbe2= (const float*)d_in[21];
    float* out = (float*)d_out;

    cudaFuncSetAttribute(k_gemm, cudaFuncAttributeMaxDynamicSharedMemorySize, 2 * BUFB);

    k_att1<<<1000, 256>>>(x, w1, b1);
    k_bnred<<<1, 1024>>>(0, 16, g1, be1);
    k_att2<<<1000, 256>>>(w2, b2);
    k_bnred<<<1, 1024>>>(1, 8, g2, be2);
    k_att3<<<1000, 256>>>(w3, b3);
    k_bnred<<<1, 1024>>>(2, 1, g3, be3);
    k_pool<<<256, 256>>>(x);
    k_gemm<<<dim3(16, 9), 256, 2 * BUFB>>>(fw1);
    k_fc1red<<<1024, 256>>>(fb1, fg1, fbe1);
    k_fc2<<<64, 256>>>(fw2, fb2);
    k_bnf2<<<256, 256>>>(fg2, fbe2);
    k_norm<<<256, 256>>>(out);
}

// round 8
// speedup vs baseline: 1.4904x; 1.4904x over previous
#include <cuda_runtime.h>
#include <cuda_bf16.h>
#include <cstdint>

#define NPTS 512000
#define KDIM 64000
#define EPS 1e-5f
#define SPLITS 9
#define KSPL 7168          // K elems per split (9*7168 >= 64000, multiple of 64)

// ---------------- device scratch (no allocation allowed) ----------------
__device__ float g_h1[NPTS * 16];
__device__ float g_h2[NPTS * 8];
__device__ float g_scr[NPTS];
__device__ float g_pa1[1000 * 32];
__device__ float g_pa2[1000 * 16];
__device__ float g_pa3[1000 * 2];
__device__ float g_bn1[32], g_bn2[16], g_bn3[2];
__device__ __nv_bfloat16 g_Ahi[256 * KDIM];
__device__ __nv_bfloat16 g_Alo[256 * KDIM];
__device__ float g_part[SPLITS * 256 * 1024];
__device__ float g_a1raw[256 * 1024];
__device__ float g_a1[256 * 1024];
__device__ float g_c2[256 * 256];

// ---------------- helpers ----------------
__device__ __forceinline__ float warp_sum(float v) {
#pragma unroll
    for (int o = 16; o; o >>= 1) v += __shfl_down_sync(0xffffffffu, v, o);
    return v;
}
__device__ __forceinline__ float warp_max(float v) {
#pragma unroll
    for (int o = 16; o; o >>= 1) v = fmaxf(v, __shfl_down_sync(0xffffffffu, v, o));
    return v;
}
__device__ __forceinline__ uint32_t s2u(const void* p) {
    uint32_t a;
    asm("{ .reg .u64 t; cvta.to.shared.u64 t, %1; cvt.u32.u64 %0, t; }" : "=r"(a) : "l"(p));
    return a;
}
__device__ __forceinline__ uint32_t pack2(__nv_bfloat16 a, __nv_bfloat16 b) {
    return ((uint32_t)__bfloat16_as_ushort(b) << 16) | (uint32_t)__bfloat16_as_ushort(a);
}
__device__ __forceinline__ void sts2(uint32_t addr, uint32_t a, uint32_t b) {
    asm volatile("st.shared.v2.b32 [%0], {%1, %2};" :: "r"(addr), "r"(a), "r"(b) : "memory");
}

#define SWZ(o) ((uint32_t)(o) ^ ((((uint32_t)(o)) >> 3) & 0x70u))

#define MMA(d, a, b0, b1)                                                        \
    asm volatile(                                                                \
        "mma.sync.aligned.m16n8k16.row.col.f32.bf16.bf16.f32 "                   \
        "{%0,%1,%2,%3},{%4,%5,%6,%7},{%8,%9},{%0,%1,%2,%3};"                     \
        : "+f"(d[0]), "+f"(d[1]), "+f"(d[2]), "+f"(d[3])                         \
        : "r"(a[0]), "r"(a[1]), "r"(a[2]), "r"(a[3]), "r"(b0), "r"(b1))

#define LDSM4(r, addr)                                                           \
    asm volatile("ldmatrix.sync.aligned.m8n8.x4.shared.b16 {%0,%1,%2,%3}, [%4];" \
        : "=r"((r)[0]), "=r"((r)[1]), "=r"((r)[2]), "=r"((r)[3]) : "r"(addr))

// ---------------- front-end ----------------
__global__ __launch_bounds__(256) void k_att1(const float* __restrict__ x,
                                              const float* __restrict__ w1,
                                              const float* __restrict__ b1) {
    __shared__ float sw[512], sb[16];
    __shared__ float rs[16][8], rq[16][8];
    int tid = threadIdx.x, wid = tid >> 5, lane = tid & 31;
    for (int i = tid; i < 512; i += 256) sw[i] = w1[i];
    if (tid < 16) sb[tid] = b1[tid];
    __syncthreads();
    float ls[16], lq[16];
#pragma unroll
    for (int j = 0; j < 16; ++j) { ls[j] = 0.f; lq[j] = 0.f; }
    size_t base = (size_t)blockIdx.x * 512;
    for (int r = 0; r < 2; ++r) {
        size_t pt = base + tid + r * 256;
        const float4* xp = (const float4*)(x + pt * 32);
        float xv[32];
#pragma unroll
        for (int q = 0; q < 8; ++q) {
            float4 t = __ldg(xp + q);
            xv[q * 4] = t.x; xv[q * 4 + 1] = t.y; xv[q * 4 + 2] = t.z; xv[q * 4 + 3] = t.w;
        }
#pragma unroll
        for (int j = 0; j < 16; ++j) {
            float a = sb[j];
#pragma unroll
            for (int c = 0; c < 32; ++c) a = fmaf(xv[c], sw[j * 32 + c], a);
            g_h1[pt * 16 + j] = a;
            ls[j] += a; lq[j] += a * a;
        }
    }
#pragma unroll
    for (int j = 0; j < 16; ++j) {
        float s = warp_sum(ls[j]), q = warp_sum(lq[j]);
        if (lane == 0) { rs[j][wid] = s; rq[j][wid] = q; }
    }
    __syncthreads();
    if (tid < 16) {
        float s = 0.f, q = 0.f;
#pragma unroll
        for (int w = 0; w < 8; ++w) { s += rs[tid][w]; q += rq[tid][w]; }
        g_pa1[blockIdx.x * 32 + tid] = s;
        g_pa1[blockIdx.x * 32 + 16 + tid] = q;
    }
}

__global__ __launch_bounds__(1024) void k_bnred(int which, int nch,
                                                const float* __restrict__ g,
                                                const float* __restrict__ be) {
    const float* part = which == 0 ? g_pa1 : which == 1 ? g_pa2 : g_pa3;
    float* out = which == 0 ? g_bn1 : which == 1 ? g_bn2 : g_bn3;
    __shared__ float sm[1024];
    int tid = threadIdx.x;
    int stride = 2 * nch;
    int w = tid & (stride - 1);
    int i0 = tid / stride;
    int per = 1024 / stride;
    float s = 0.f;
    for (int i = i0; i < 1000; i += per) s += part[i * stride + w];
    sm[tid] = s;
    __syncthreads();
    for (int off = 512; off >= stride; off >>= 1) {
        if (tid < off) sm[tid] += sm[tid + off];
        __syncthreads();
    }
    if (tid < nch) {
        float mean = sm[tid] * (1.f / 512000.f);
        float var = sm[nch + tid] * (1.f / 512000.f) - mean * mean;
        float sc = rsqrtf(var + EPS) * g[tid];
        out[tid] = sc;
        out[nch + tid] = be[tid] - mean * sc;
    }
}

__global__ __launch_bounds__(256) void k_att2(const float* __restrict__ w2,
                                              const float* __restrict__ b2) {
    __shared__ float sw[128], sb[8], ssc[16], ssh[16];
    __shared__ float rs[8][8], rq[8][8];
    int tid = threadIdx.x, wid = tid >> 5, lane = tid & 31;
    for (int i = tid; i < 128; i += 256) sw[i] = w2[i];
    if (tid < 8) sb[tid] = b2[tid];
    if (tid < 16) { ssc[tid] = g_bn1[tid]; ssh[tid] = g_bn1[16 + tid]; }
    __syncthreads();
    float ls[8], lq[8];
#pragma unroll
    for (int j = 0; j < 8; ++j) { ls[j] = 0.f; lq[j] = 0.f; }
    size_t base = (size_t)blockIdx.x * 512;
    for (int r = 0; r < 2; ++r) {
        size_t pt = base + tid + r * 256;
        float ha[16];
#pragma unroll
        for (int c = 0; c < 16; ++c)
            ha[c] = fmaxf(0.f, fmaf(g_h1[pt * 16 + c], ssc[c], ssh[c]));
#pragma unroll
        for (int j = 0; j < 8; ++j) {
            float a = sb[j];
#pragma unroll
            for (int c = 0; c < 16; ++c) a = fmaf(ha[c], sw[j * 16 + c], a);
            g_h2[pt * 8 + j] = a;
            ls[j] += a; lq[j] += a * a;
        }
    }
#pragma unroll
    for (int j = 0; j < 8; ++j) {
        float s = warp_sum(ls[j]), q = warp_sum(lq[j]);
        if (lane == 0) { rs[j][wid] = s; rq[j][wid] = q; }
    }
    __syncthreads();
    if (tid < 8) {
        float s = 0.f, q = 0.f;
#pragma unroll
        for (int w = 0; w < 8; ++w) { s += rs[tid][w]; q += rq[tid][w]; }
        g_pa2[blockIdx.x * 16 + tid] = s;
        g_pa2[blockIdx.x * 16 + 8 + tid] = q;
    }
}

__global__ __launch_bounds__(256) void k_att3(const float* __restrict__ w3,
                                              const float* __restrict__ b3) {
    __shared__ float sw[8], ssc[8], ssh[8], sb3;
    __shared__ float rs[8], rq[8];
    int tid = threadIdx.x, wid = tid >> 5, lane = tid & 31;
    if (tid < 8) { sw[tid] = w3[tid]; ssc[tid] = g_bn2[tid]; ssh[tid] = g_bn2[8 + tid]; }
    if (tid == 0) sb3 = b3[0];
    __syncthreads();
    float ls = 0.f, lq = 0.f;
    size_t base = (size_t)blockIdx.x * 512;
    for (int r = 0; r < 2; ++r) {
        size_t pt = base + tid + r * 256;
        float a = sb3;
#pragma unroll
        for (int c = 0; c < 8; ++c)
            a = fmaf(fmaxf(0.f, fmaf(g_h2[pt * 8 + c], ssc[c], ssh[c])), sw[c], a);
        g_scr[pt] = a;
        ls += a; lq += a * a;
    }
    ls = warp_sum(ls); lq = warp_sum(lq);
    if (lane == 0) { rs[wid] = ls; rq[wid] = lq; }
    __syncthreads();
    if (tid == 0) {
        float s = 0.f, q = 0.f;
#pragma unroll
        for (int w = 0; w < 8; ++w) { s += rs[w]; q += rq[w]; }
        g_pa3[blockIdx.x * 2] = s;
        g_pa3[blockIdx.x * 2 + 1] = q;
    }
}

// ---------------- per-segment softmax + pooled A (bf16 hi/lo) ----------------
__global__ __launch_bounds__(256) void k_pool(const float* __restrict__ x) {
    __shared__ float s[2000];
    __shared__ float red[8];
    __shared__ float m_sh, sum_sh;
    int b = blockIdx.x, tid = threadIdx.x, wid = tid >> 5, lane = tid & 31;
    float sc = g_bn3[0], sh = g_bn3[1];
    float lm = -1e30f;
    for (int p = tid; p < 2000; p += 256) {
        float v = fmaxf(0.f, fmaf(g_scr[(size_t)b * 2000 + p], sc, sh));
        s[p] = v;
        lm = fmaxf(lm, v);
    }
    lm = warp_max(lm);
    if (!lane) red[wid] = lm;
    __syncthreads();
    if (tid == 0) {
        float m = red[0];
#pragma unroll
        for (int i = 1; i < 8; ++i) m = fmaxf(m, red[i]);
        m_sh = m;
    }
    __syncthreads();
    float m = m_sh, le = 0.f;
    for (int p = tid; p < 2000; p += 256) {
        float e = expf(s[p] - m);
        s[p] = e;
        le += e;
    }
    le = warp_sum(le);
    if (!lane) red[wid] = le;
    __syncthreads();
    if (tid == 0) {
        float t = 0.f;
#pragma unroll
        for (int i = 0; i < 8; ++i) t += red[i];
        sum_sh = t;
    }
    __syncthreads();
    float inv = 1.f / sum_sh;
    for (int p = tid; p < 2000; p += 256) {
        float a = s[p] * inv;
        const float4* xp = (const float4*)(x + ((size_t)b * 2000 + p) * 32);
        size_t ob = (size_t)b * KDIM + (size_t)p * 32;
#pragma unroll
        for (int q = 0; q < 8; ++q) {
            float4 t = xp[q];
            float v0 = t.x * a, v1 = t.y * a, v2 = t.z * a, v3 = t.w * a;
            __nv_bfloat16 h0 = __float2bfloat16(v0), h1 = __float2bfloat16(v1);
            __nv_bfloat16 h2 = __float2bfloat16(v2), h3 = __float2bfloat16(v3);
            __nv_bfloat16 l0 = __float2bfloat16(v0 - __bfloat162float(h0));
            __nv_bfloat16 l1 = __float2bfloat16(v1 - __bfloat162float(h1));
            __nv_bfloat16 l2 = __float2bfloat16(v2 - __bfloat162float(h2));
            __nv_bfloat16 l3 = __float2bfloat16(v3 - __bfloat162float(h3));
            ((uint2*)(g_Ahi + ob))[q] = make_uint2(pack2(h0, h1), pack2(h2, h3));
            ((uint2*)(g_Alo + ob))[q] = make_uint2(pack2(l0, l1), pack2(l2, l3));
        }
    }
}

// ---------------- fc1 GEMM (HMMA): M=128, N=128, K-step 64, split-K 9 ----------------
// stage layout: [0] Ahi 16K | [16K] Alo 16K | [32K] Whi 16K | [48K] Wlo 16K | [64K] Wf32 32K
#define GBUF 98304
__global__ __launch_bounds__(256, 1) void k_gemm3(const float* __restrict__ fw1) {
    extern __shared__ char smraw[];
    char* sm = (char*)(((uintptr_t)smraw + 1023) & ~(uintptr_t)1023);
    int tid = threadIdx.x, wid = tid >> 5, lane = tid & 31;
    int n0 = blockIdx.x * 128;
    int m0 = blockIdx.y * 128;
    int split = blockIdx.z;
    int kbeg = split * KSPL;
    int klen = min(KSPL, KDIM - kbeg);
    int steps = klen >> 6;
    int wm = wid >> 1, wn = wid & 1;        // warp tile: m32 x n64
    int mt = wm * 32, ntb = wn * 64;

    float acc[2][8][4];
#pragma unroll
    for (int a = 0; a < 2; ++a)
#pragma unroll
        for (int b = 0; b < 8; ++b)
#pragma unroll
            for (int c = 0; c < 4; ++c) acc[a][b][c] = 0.f;

    // async fill: A hi/lo swizzled + W fp32 raw (all cp.async, no blocking loads)
    auto fill = [&](char* buf, int k0) {
#pragma unroll
        for (int i = 0; i < 8; ++i) {
            int cid = tid + i * 256;
            int plane = cid >> 10, idx = cid & 1023;
            int row = idx >> 3, chunk = idx & 7;
            const __nv_bfloat16* src = (plane ? g_Alo : g_Ahi)
                + (size_t)(m0 + row) * KDIM + k0 + chunk * 8;
            uint32_t d = s2u(buf + plane * 16384 + SWZ(row * 128 + chunk * 16));
            asm volatile("cp.async.cg.shared.global [%0],[%1],16;" :: "r"(d), "l"(src));
        }
#pragma unroll
        for (int i = 0; i < 8; ++i) {
            int c = tid + i * 256;
            int row = c >> 4, kc = c & 15;
            const float* src = fw1 + (size_t)(n0 + row) * KDIM + k0 + kc * 4;
            uint32_t d = s2u(buf + 65536 + c * 16);
            asm volatile("cp.async.cg.shared.global [%0],[%1],16;" :: "r"(d), "l"(src));
        }
        asm volatile("cp.async.commit_group;" ::: "memory");
    };

    // convert staged W fp32 -> bf16 hi (truncate) + lo, into swizzled region
    auto convW = [&](char* buf) {
#pragma unroll
        for (int i = 0; i < 8; ++i) {
            int c = tid + i * 256;
            float4 f = *(const float4*)(buf + 65536 + c * 16);
            int row = c >> 4, kc = c & 15;
            uint32_t b0 = __float_as_uint(f.x), b1 = __float_as_uint(f.y);
            uint32_t b2 = __float_as_uint(f.z), b3 = __float_as_uint(f.w);
            uint32_t hi0 = __byte_perm(b0, b1, 0x7632);
            uint32_t hi1 = __byte_perm(b2, b3, 0x7632);
            float l0 = f.x - __uint_as_float(b0 & 0xffff0000u);
            float l1 = f.y - __uint_as_float(b1 & 0xffff0000u);
            float l2 = f.z - __uint_as_float(b2 & 0xffff0000u);
            float l3 = f.w - __uint_as_float(b3 & 0xffff0000u);
            uint32_t lo0, lo1;
            asm("cvt.rn.bf16x2.f32 %0, %1, %2;" : "=r"(lo0) : "f"(l1), "f"(l0));
            asm("cvt.rn.bf16x2.f32 %0, %1, %2;" : "=r"(lo1) : "f"(l3), "f"(l2));
            uint32_t off = SWZ(row * 128 + kc * 8);
            sts2(s2u(buf + 32768 + off), hi0, hi1);
            sts2(s2u(buf + 49152 + off), lo0, lo1);
        }
    };

    fill(sm, kbeg);

    for (int s = 0; s < steps; ++s) {
        char* cur = sm + (s & 1) * GBUF;
        asm volatile("cp.async.wait_group 0;" ::: "memory");
        __syncthreads();                       // cur data complete; prev consume done
        if (s + 1 < steps) fill(sm + ((s + 1) & 1) * GBUF, kbeg + (s + 1) * 64);
        convW(cur);
        __syncthreads();                       // W bf16 visible
        uint32_t abase = s2u(cur), wbase = s2u(cur + 32768);
#pragma unroll
        for (int g = 0; g < 4; ++g) {
            int c0b = g * 32;
            uint32_t aH[2][4], aL[2][4];
#pragma unroll
            for (int mi = 0; mi < 2; ++mi) {
                int row = mt + mi * 16 + (lane & 7) + ((lane >> 3) & 1) * 8;
                int colb = c0b + (lane >> 4) * 16;
                uint32_t off = SWZ(row * 128 + colb);
                LDSM4(aH[mi], abase + off);
                LDSM4(aL[mi], abase + 16384 + off);
            }
            uint32_t bH[4][4], bL[4][4];
#pragma unroll
            for (int j = 0; j < 4; ++j) {
                int row = ntb + j * 16 + (lane & 7) + (lane >> 4) * 8;
                int colb = c0b + ((lane >> 3) & 1) * 16;
                uint32_t off = SWZ(row * 128 + colb);
                LDSM4(bH[j], wbase + off);
                LDSM4(bL[j], wbase + 16384 + off);
            }
#pragma unroll
            for (int mi = 0; mi < 2; ++mi)
#pragma unroll
                for (int j = 0; j < 4; ++j) {
                    MMA(acc[mi][j * 2], aH[mi], bH[j][0], bH[j][1]);
                    MMA(acc[mi][j * 2], aH[mi], bL[j][0], bL[j][1]);
                    MMA(acc[mi][j * 2], aL[mi], bH[j][0], bH[j][1]);
                    MMA(acc[mi][j * 2 + 1], aH[mi], bH[j][2], bH[j][3]);
                    MMA(acc[mi][j * 2 + 1], aH[mi], bL[j][2], bL[j][3]);
                    MMA(acc[mi][j * 2 + 1], aL[mi], bH[j][2], bH[j][3]);
                }
        }
    }

    // epilogue: split-K partials
    float* dst = g_part + (size_t)split * 256 * 1024;
#pragma unroll
    for (int mi = 0; mi < 2; ++mi)
#pragma unroll
        for (int ni = 0; ni < 8; ++ni) {
            int row = m0 + mt + mi * 16 + (lane >> 2);
            int col = n0 + ntb + ni * 8 + (lane & 3) * 2;
            *(float2*)(dst + (size_t)row * 1024 + col) =
                make_float2(acc[mi][ni][0], acc[mi][ni][1]);
            *(float2*)(dst + (size_t)(row + 8) * 1024 + col) =
                make_float2(acc[mi][ni][2], acc[mi][ni][3]);
        }
}

// ---------------- split-K sum (coalesced) + bias ----------------
__global__ __launch_bounds__(256) void k_red1(const float* __restrict__ fb1) {
    int row = blockIdx.x;
#pragma unroll
    for (int j = 0; j < 4; ++j) {
        int col = threadIdx.x + j * 256;
        float v = fb1[col];
#pragma unroll
        for (int s = 0; s < SPLITS; ++s)
            v += g_part[((size_t)(s * 256 + row)) * 1024 + col];
        g_a1raw[(size_t)row * 1024 + col] = v;
    }
}

// ---------------- per-col BN + relu ----------------
__global__ __launch_bounds__(256) void k_fc1bn(const float* __restrict__ fg1,
                                               const float* __restrict__ fbe1) {
    int col = blockIdx.x, r = threadIdx.x;
    int w = r >> 5, lane = r & 31;
    float v = g_a1raw[(size_t)r * 1024 + col];
    __shared__ float red[16];
    __shared__ float mv[2];
    float s1 = warp_sum(v), s2 = warp_sum(v * v);
    if (!lane) { red[w] = s1; red[8 + w] = s2; }
    __syncthreads();
    if (r == 0) {
        float a = 0.f, b = 0.f;
#pragma unroll
        for (int i = 0; i < 8; ++i) { a += red[i]; b += red[8 + i]; }
        float m = a * (1.f / 256.f);
        mv[0] = m;
        mv[1] = b * (1.f / 256.f) - m * m;
    }
    __syncthreads();
    float sc = rsqrtf(mv[1] + EPS) * fg1[col];
    float sh = fbe1[col] - mv[0] * sc;
    g_a1[(size_t)r * 1024 + col] = fmaxf(0.f, fmaf(v, sc, sh));
}

// ---------------- fc2 ----------------
__global__ __launch_bounds__(256) void k_fc2(const float* __restrict__ fw2,
                                             const float* __restrict__ fb2) {
    __shared__ float sa[32][129], sw[32][129];
    int tid = threadIdx.x;
    int rt = blockIdx.x >> 3, ct = blockIdx.x & 7;
    int tx = tid & 31, ty = tid >> 5;
    float accv[4] = {0.f, 0.f, 0.f, 0.f};
    for (int kc = 0; kc < 1024; kc += 128) {
#pragma unroll
        for (int i = 0; i < 4; ++i) {
            int id = tid + i * 256;
            int row = id >> 5, qq = id & 31;
            float4 va = *(const float4*)(g_a1 + (size_t)(rt * 32 + row) * 1024 + kc + qq * 4);
            sa[row][qq * 4 + 0] = va.x; sa[row][qq * 4 + 1] = va.y;
            sa[row][qq * 4 + 2] = va.z; sa[row][qq * 4 + 3] = va.w;
            float4 vw = *(const float4*)(fw2 + (size_t)(ct * 32 + row) * 1024 + kc + qq * 4);
            sw[row][qq * 4 + 0] = vw.x; sw[row][qq * 4 + 1] = vw.y;
            sw[row][qq * 4 + 2] = vw.z; sw[row][qq * 4 + 3] = vw.w;
        }
        __syncthreads();
#pragma unroll 8
        for (int k = 0; k < 128; ++k) {
            float wv = sw[tx][k];
#pragma unroll
            for (int i = 0; i < 4; ++i) accv[i] = fmaf(sa[ty + 8 * i][k], wv, accv[i]);
        }
        __syncthreads();
    }
    float bias = fb2[ct * 32 + tx];
#pragma unroll
    for (int i = 0; i < 4; ++i)
        g_c2[(size_t)(rt * 32 + ty + 8 * i) * 256 + ct * 32 + tx] = accv[i] + bias;
}

__global__ __launch_bounds__(256) void k_bnf2(const float* __restrict__ fg2,
                                              const float* __restrict__ fbe2) {
    int n = blockIdx.x, r = threadIdx.x, w = r >> 5, lane = r & 31;
    float v = g_c2[(size_t)r * 256 + n];
    __shared__ float red[16];
    __shared__ float mv[2];
    float s1 = warp_sum(v), s2 = warp_sum(v * v);
    if (!lane) { red[w] = s1; red[8 + w] = s2; }
    __syncthreads();
    if (r == 0) {
        float a = 0.f, b = 0.f;
#pragma unroll
        for (int i = 0; i < 8; ++i) { a += red[i]; b += red[8 + i]; }
        float m = a * (1.f / 256.f);
        mv[0] = m;
        mv[1] = b * (1.f / 256.f) - m * m;
    }
    __syncthreads();
    float sc = rsqrtf(mv[1] + EPS) * fg2[n];
    float sh = fbe2[n] - mv[0] * sc;
    g_c2[(size_t)r * 256 + n] = fmaxf(0.f, fmaf(v, sc, sh));
}

__global__ __launch_bounds__(256) void k_norm(float* __restrict__ out) {
    int row = blockIdx.x, c = threadIdx.x, w = c >> 5, lane = c & 31;
    float v = g_c2[(size_t)row * 256 + c];
    __shared__ float red[8];
    __shared__ float nrm;
    float s = warp_sum(v * v);
    if (!lane) red[w] = s;
    __syncthreads();
    if (c == 0) {
        float t = 0.f;
#pragma unroll
        for (int i = 0; i < 8; ++i) t += red[i];
        nrm = fmaxf(sqrtf(t), 1e-12f);
    }
    __syncthreads();
    out[(size_t)row * 256 + c] = v / nrm;
}

// ---------------- launch ----------------
extern "C" void kernel_launch(void* const* d_in, const int* in_sizes, int n_in,
                              void* d_out, int out_size) {
    const float* x   = (const float*)d_in[0];
    const float* w1  = (const float*)d_in[2];
    const float* b1  = (const float*)d_in[3];
    const float* g1  = (const float*)d_in[4];
    const float* be1 = (const float*)d_in[5];
    const float* w2  = (const float*)d_in[6];
    const float* b2  = (const float*)d_in[7];
    const float* g2  = (const float*)d_in[8];
    const float* be2 = (const float*)d_in[9];
    const float* w3  = (const float*)d_in[10];
    const float* b3  = (const float*)d_in[11];
    const float* g3  = (const float*)d_in[12];
    const float* be3 = (const float*)d_in[13];
    const float* fw1 = (const float*)d_in[14];
    const float* fb1 = (const float*)d_in[15];
    const float* fg1 = (const float*)d_in[16];
    const float* fbe1= (const float*)d_in[17];
    const float* fw2 = (const float*)d_in[18];
    const float* fb2 = (const float*)d_in[19];
    const float* fg2 = (const float*)d_in[20];
    const float* fbe2= (const float*)d_in[21];
    float* out = (float*)d_out;

    cudaFuncSetAttribute(k_gemm3, cudaFuncAttributeMaxDynamicSharedMemorySize,
                         2 * GBUF + 1024);

    k_att1<<<1000, 256>>>(x, w1, b1);
    k_bnred<<<1, 1024>>>(0, 16, g1, be1);
    k_att2<<<1000, 256>>>(w2, b2);
    k_bnred<<<1, 1024>>>(1, 8, g2, be2);
    k_att3<<<1000, 256>>>(w3, b3);
    k_bnred<<<1, 1024>>>(2, 1, g3, be3);
    k_pool<<<256, 256>>>(x);
    k_gemm3<<<dim3(8, 2, SPLITS), 256, 2 * GBUF + 1024>>>(fw1);
    k_red1<<<256, 256>>>(fb1);
    k_fc1bn<<<1024, 256>>>(fg1, fbe1);
    k_fc2<<<64, 256>>>(fw2, fb2);
    k_bnf2<<<256, 256>>>(fg2, fbe2);
    k_norm<<<256, 256>>>(out);
}